// round 5
// baseline (speedup 1.0000x reference)
#include <cuda_runtime.h>
#include <cstdint>

// Problem constants (fixed shapes)
#define NODES 32768       // B*N
#define NPB   16384       // nodes per batch
#define FDIM  64          // node feature dim (F)
#define EDIM  16          // edge feature dim (E)
#define KNB   32          // neighbors per node (K)
#define KDIM  1024        // F*E, GEMM reduction dim
#define KCH   32          // GEMM k-chunk
#define NC    (KDIM / KCH)

// Scratch (allocation-free rule: __device__ globals)
// T stored pre-split: per node, 32 chunks x 16 k-pairs x {bf16x2_hi, bf16x2_lo}
__device__ __align__(128) uint32_t g_Tb[(size_t)NODES * KDIM];   // 128 MB
// W pre-packed in bf16 MMA-fragment order:
// [c(32)][q(2)][spl(2)][nt(8)][lane(32)][2 x u32]
__device__ __align__(128) uint2 g_Wp[NC * 2 * 2 * 8 * 32];       // 256 KB

typedef unsigned long long u64;

// ---------------- f32x2 helpers (stage 1) ----------------
__device__ __forceinline__ u64 pack2(float lo, float hi) {
    u64 r; asm("mov.b64 %0, {%1, %2};" : "=l"(r) : "f"(lo), "f"(hi)); return r;
}
__device__ __forceinline__ void unpack2(u64 v, float& lo, float& hi) {
    asm("mov.b64 {%0, %1}, %2;" : "=f"(lo), "=f"(hi) : "l"(v));
}
__device__ __forceinline__ u64 ffma2(u64 a, u64 b, u64 c) {
    u64 d; asm("fma.rn.f32x2 %0, %1, %2, %3;" : "=l"(d) : "l"(a), "l"(b), "l"(c)); return d;
}

// ---------------- bf16 helpers ----------------
__device__ __forceinline__ uint32_t packbf(float o, float e) {   // low half = e
    uint32_t r; asm("cvt.rn.bf16x2.f32 %0, %1, %2;" : "=r"(r) : "f"(o), "f"(e)); return r;
}
// split packed f32 pair (even,odd) -> {hi bf16x2, lo bf16x2}
__device__ __forceinline__ void pair_split(u64 v, uint32_t& h, uint32_t& l) {
    float fe, fo; unpack2(v, fe, fo);
    h = packbf(fo, fe);
    float he = __uint_as_float(h << 16);
    float ho = __uint_as_float(h & 0xffff0000u);
    l = packbf(fo - ho, fe - he);
}
__device__ __forceinline__ uint32_t smem_u32(const void* p) {
    uint32_t a;
    asm("{ .reg .u64 t; cvta.to.shared.u64 t, %1; cvt.u32.u64 %0, t; }" : "=r"(a) : "l"(p));
    return a;
}
__device__ __forceinline__ void cp_async16(uint32_t dst, const void* src) {
    asm volatile("cp.async.ca.shared.global [%0], [%1], 16;" :: "r"(dst), "l"(src) : "memory");
}
__device__ __forceinline__ void cp_commit() {
    asm volatile("cp.async.commit_group;" ::: "memory");
}
__device__ __forceinline__ void cp_wait1() {
    asm volatile("cp.async.wait_group 1;" ::: "memory");
}
__device__ __forceinline__ void cp_wait0() {
    asm volatile("cp.async.wait_group 0;" ::: "memory");
}
// m16n8k16 bf16 mma, accumulate in place
__device__ __forceinline__ void mma16(float* c, const uint32_t* a, uint32_t b0, uint32_t b1) {
    asm volatile(
        "mma.sync.aligned.m16n8k16.row.col.f32.bf16.bf16.f32 "
        "{%0,%1,%2,%3}, {%4,%5,%6,%7}, {%8,%9}, {%0,%1,%2,%3};"
        : "+f"(c[0]), "+f"(c[1]), "+f"(c[2]), "+f"(c[3])
        : "r"(a[0]), "r"(a[1]), "r"(a[2]), "r"(a[3]), "r"(b0), "r"(b1));
}

// ---------------------------------------------------------------------------
// Kernel 1: stage 1 — gather + rank-32 outer product per node, bf16 hi/lo out.
// One warp per node; depth-8 gather pipeline. First 64 blocks also pack W.
// ---------------------------------------------------------------------------
__global__ __launch_bounds__(256) void stage1_kernel(
    const float* __restrict__ nodes,
    const int*   __restrict__ nlist,
    const float* __restrict__ edges,
    const float* __restrict__ w)
{
    // ---- embedded W pack (first 64 blocks; 16384 work items) ----
    if (blockIdx.x < 64) {
        int idx  = blockIdx.x * 256 + threadIdx.x;
        int lane = idx & 31;
        int nt   = (idx >> 5) & 7;
        int q    = (idx >> 8) & 1;
        int c    = idx >> 9;
        int tig  = lane & 3;
        int grp  = lane >> 2;
        int m    = nt * 8 + grp;
        int k0   = c * KCH + q * 16 + 2 * tig;
        float v[4];
#pragma unroll
        for (int s = 0; s < 4; ++s) {
            int k = k0 + (s >> 1) * 8 + (s & 1);
            int l = k >> 4, n = k & 15;
            v[s] = w[l * (FDIM * EDIM) + m * EDIM + n] * 0.03125f;
        }
        uint32_t b0h = packbf(v[1], v[0]);
        uint32_t b1h = packbf(v[3], v[2]);
        uint32_t b0l = packbf(v[1] - __uint_as_float(b0h & 0xffff0000u),
                              v[0] - __uint_as_float(b0h << 16));
        uint32_t b1l = packbf(v[3] - __uint_as_float(b1h & 0xffff0000u),
                              v[2] - __uint_as_float(b1h << 16));
        int base = ((c * 2 + q) * 2) * 8 + nt;
        g_Wp[(size_t)base * 32 + lane]       = make_uint2(b0h, b1h);
        g_Wp[(size_t)(base + 8) * 32 + lane] = make_uint2(b0l, b1l);
    }

    __shared__ float se[8][512];

    const int warp = threadIdx.x >> 5;
    const int lane = threadIdx.x & 31;
    const int node = (blockIdx.x << 3) + warp;
    const int b    = node >> 14;
    const float* nbase = nodes + (size_t)b * NPB * FDIM;

    const float4* e4 = (const float4*)(edges + (size_t)node * (KNB * EDIM));
    float4* s4 = (float4*)se[warp];
    s4[lane]       = e4[lane];
    s4[lane + 32]  = e4[lane + 32];
    s4[lane + 64]  = e4[lane + 64];
    s4[lane + 96]  = e4[lane + 96];
    int idx = nlist[node * KNB + lane];
    __syncwarp();

    u64 T0[8], T1[8];
#pragma unroll
    for (int p = 0; p < 8; ++p) { T0[p] = 0ull; T1[p] = 0ull; }

    float2 xq[8];
#pragma unroll
    for (int j = 0; j < 8; ++j) {
        int nb = __shfl_sync(0xffffffffu, idx, j);
        xq[j] = *(const float2*)(nbase + (size_t)nb * FDIM + 2 * lane);
    }

#pragma unroll
    for (int j = 0; j < KNB; ++j) {
        float2 xc = xq[j & 7];
        if (j + 8 < KNB) {
            int nb = __shfl_sync(0xffffffffu, idx, j + 8);
            xq[j & 7] = *(const float2*)(nbase + (size_t)nb * FDIM + 2 * lane);
        }
        u64 xx0 = pack2(xc.x, xc.x);
        u64 xx1 = pack2(xc.y, xc.y);
        const ulonglong2* ep = (const ulonglong2*)&se[warp][j * EDIM];
        ulonglong2 e01 = ep[0];
        ulonglong2 e23 = ep[1];
        ulonglong2 e45 = ep[2];
        ulonglong2 e67 = ep[3];
        T0[0] = ffma2(xx0, e01.x, T0[0]);  T0[1] = ffma2(xx0, e01.y, T0[1]);
        T0[2] = ffma2(xx0, e23.x, T0[2]);  T0[3] = ffma2(xx0, e23.y, T0[3]);
        T0[4] = ffma2(xx0, e45.x, T0[4]);  T0[5] = ffma2(xx0, e45.y, T0[5]);
        T0[6] = ffma2(xx0, e67.x, T0[6]);  T0[7] = ffma2(xx0, e67.y, T0[7]);
        T1[0] = ffma2(xx1, e01.x, T1[0]);  T1[1] = ffma2(xx1, e01.y, T1[1]);
        T1[2] = ffma2(xx1, e23.x, T1[2]);  T1[3] = ffma2(xx1, e23.y, T1[3]);
        T1[4] = ffma2(xx1, e45.x, T1[4]);  T1[5] = ffma2(xx1, e45.y, T1[5]);
        T1[6] = ffma2(xx1, e67.x, T1[6]);  T1[7] = ffma2(xx1, e67.y, T1[7]);
    }

    // split to bf16 hi/lo pairs and store lane's chunk (k = 32*lane..+31):
    // layout per node: [chunk(=lane)][pair j 0..15][{hi,lo}] u32, 128 B / lane
    uint4 o[8];
#pragma unroll
    for (int p = 0; p < 8; ++p) {
        uint32_t h0, l0, h1, l1;
        pair_split(T0[p], h0, l0);          // pairs j=0..7  (k = 32lane + 2p,2p+1)
        pair_split(T1[p], h1, l1);          // pairs j=8..15 (k = 32lane+16+2p,..)
        o[p >> 1].x = (p & 1) ? o[p >> 1].x : h0;   // fill below instead
        (void)h1; (void)l1; (void)l0;
        // (restructured below)
    }
    // simple direct construction (compiler folds):
    {
        uint32_t hv[16], lv[16];
#pragma unroll
        for (int p = 0; p < 8; ++p) pair_split(T0[p], hv[p],     lv[p]);
#pragma unroll
        for (int p = 0; p < 8; ++p) pair_split(T1[p], hv[8 + p], lv[8 + p]);
        uint4* tp = (uint4*)(g_Tb + (size_t)node * KDIM + lane * 32);
#pragma unroll
        for (int p = 0; p < 8; ++p)
            tp[p] = make_uint4(hv[2*p], lv[2*p], hv[2*p+1], lv[2*p+1]);
    }
}

// ---------------------------------------------------------------------------
// Kernel 2: bf16 mma.sync GEMM, 3-split fp32 emulation (AhBh + AlBh + AhBl).
// A arrives pre-split from stage1: one LDS.64 = {hi,lo} fragment register pair.
// CTA: 128 rows x 64 cols, 4 warps, warp = 32 rows x 64 cols (2 mt x 8 nt).
// ---------------------------------------------------------------------------
#define A_STRIDE 40                        // u32 per row (conflict-free)
#define A_BUF    (128 * A_STRIDE)          // u32 per buffer
#define B_BUF    2048                      // u32 per buffer
#define GEMM_SMEM (2 * A_BUF * 4 + 2 * B_BUF * 4)   // 57344 B

__global__ __launch_bounds__(128, 2) void gemm_bf16_kernel(float* __restrict__ out)
{
    extern __shared__ char smraw[];
    uint32_t* As = (uint32_t*)smraw;                       // [2][128][40]
    uint32_t* Bs = (uint32_t*)(smraw + 2 * A_BUF * 4);     // [2][2048]

    const int tid  = threadIdx.x;
    const int lane = tid & 31;
    const int wid  = tid >> 5;
    const int tig  = lane & 3;
    const int grp  = lane >> 2;
    const int rbase = blockIdx.x * 128;
    const int wrow  = wid * 32;

    const uint32_t* aSrc = g_Tb + (size_t)(rbase + tid) * KDIM;   // node row
    const char*     bSrc = (const char*)g_Wp;

    float acc[2][8][4];
#pragma unroll
    for (int mt = 0; mt < 2; ++mt)
#pragma unroll
        for (int nt = 0; nt < 8; ++nt)
#pragma unroll
            for (int r = 0; r < 4; ++r) acc[mt][nt][r] = 0.0f;

#define STAGE(c, buf)                                                          \
    do {                                                                       \
        uint32_t ad = smem_u32(As + (buf) * A_BUF + tid * A_STRIDE);           \
        const uint32_t* as_ = aSrc + (c) * 32;                                 \
        _Pragma("unroll")                                                      \
        for (int i = 0; i < 8; ++i) cp_async16(ad + i * 16, as_ + i * 4);      \
        uint32_t bd = smem_u32(Bs + (buf) * B_BUF) + tid * 64;                 \
        const char* bs_ = bSrc + (size_t)(c) * 8192 + tid * 64;                \
        _Pragma("unroll")                                                      \
        for (int i = 0; i < 4; ++i) cp_async16(bd + i * 16, bs_ + i * 16);     \
        cp_commit();                                                           \
    } while (0)

    STAGE(0, 0);

    for (int c = 0; c < NC; ++c) {
        const int buf = c & 1;
        if (c + 1 < NC) { STAGE(c + 1, buf ^ 1); cp_wait1(); }
        else            { cp_wait0(); }
        __syncthreads();

        const uint32_t* Ab = As + buf * A_BUF;
        const uint32_t* Bb = Bs + buf * B_BUF;

#pragma unroll
        for (int q = 0; q < 2; ++q) {
            uint32_t ah[2][4], al[2][4];
#pragma unroll
            for (int mt = 0; mt < 2; ++mt) {
                const uint32_t* pr = Ab + (wrow + mt * 16 + grp) * A_STRIDE + q * 16 + 2 * tig;
                uint2 v0 = *(const uint2*)(pr);                      // a0 {hi,lo}
                uint2 v1 = *(const uint2*)(pr + 8 * A_STRIDE);       // a1
                uint2 v2 = *(const uint2*)(pr + 8);                  // a2 (pair +4)
                uint2 v3 = *(const uint2*)(pr + 8 * A_STRIDE + 8);   // a3
                ah[mt][0] = v0.x; al[mt][0] = v0.y;
                ah[mt][1] = v1.x; al[mt][1] = v1.y;
                ah[mt][2] = v2.x; al[mt][2] = v2.y;
                ah[mt][3] = v3.x; al[mt][3] = v3.y;
            }
#pragma unroll
            for (int nt = 0; nt < 8; ++nt) {
                uint2 bh = *(const uint2*)(Bb + ((q * 2 + 0) * 8 + nt) * 64 + lane * 2);
                uint2 bl = *(const uint2*)(Bb + ((q * 2 + 1) * 8 + nt) * 64 + lane * 2);
#pragma unroll
                for (int mt = 0; mt < 2; ++mt) {
                    mma16(acc[mt][nt], ah[mt], bh.x, bh.y);
                    mma16(acc[mt][nt], al[mt], bh.x, bh.y);
                    mma16(acc[mt][nt], ah[mt], bl.x, bl.y);
                }
            }
        }
        __syncthreads();
    }

#pragma unroll
    for (int mt = 0; mt < 2; ++mt) {
#pragma unroll
        for (int nt = 0; nt < 8; ++nt) {
            int row = rbase + wrow + mt * 16 + grp;
            int col = nt * 8 + 2 * tig;
            *(float2*)(out + (size_t)row * FDIM + col) =
                make_float2(acc[mt][nt][0], acc[mt][nt][1]);
            *(float2*)(out + (size_t)(row + 8) * FDIM + col) =
                make_float2(acc[mt][nt][2], acc[mt][nt][3]);
        }
    }
#undef STAGE
}

// ---------------------------------------------------------------------------
extern "C" void kernel_launch(void* const* d_in, const int* in_sizes, int n_in,
                              void* d_out, int out_size) {
    const float* nodes = (const float*)d_in[0];   // [2,16384,64] f32
    const int*   nlist = (const int*)  d_in[1];   // [2,16384,32] i32
    const float* edges = (const float*)d_in[2];   // [2,16384,32,16] f32
    const float* w     = (const float*)d_in[3];   // [64,64,16] f32
    float* out = (float*)d_out;                   // [2,16384,64] f32

    cudaFuncSetAttribute(gemm_bf16_kernel,
                         cudaFuncAttributeMaxDynamicSharedMemorySize, GEMM_SMEM);

    stage1_kernel<<<NODES / 8, 256>>>(nodes, nlist, edges, w);
    gemm_bf16_kernel<<<NODES / 128, 128, GEMM_SMEM>>>(out);
}

// round 6
// speedup vs baseline: 1.1793x; 1.1793x over previous
#include <cuda_runtime.h>
#include <cstdint>

// Problem constants (fixed shapes)
#define NODES 32768       // B*N
#define NPB   16384       // nodes per batch
#define FDIM  64          // node feature dim (F)
#define EDIM  16          // edge feature dim (E)
#define KNB   32          // neighbors per node (K)
#define KDIM  1024        // F*E, GEMM reduction dim
#define KCH   32          // GEMM k-chunk
#define NC    (KDIM / KCH)

// Scratch (allocation-free rule: __device__ globals)
// T stored pre-split: per node, 32 chunks x 16 k-pairs x {bf16x2_hi, bf16x2_lo}
__device__ __align__(128) uint32_t g_Tb[(size_t)NODES * KDIM];   // 128 MB
// W pre-packed in bf16 MMA-fragment order:
// [c(32)][q(2)][spl(2)][nt(8)][lane(32)][2 x u32]
__device__ __align__(128) uint2 g_Wp[NC * 2 * 2 * 8 * 32];       // 256 KB

typedef unsigned long long u64;

// ---------------- f32x2 helpers (stage 1) ----------------
__device__ __forceinline__ u64 pack2(float lo, float hi) {
    u64 r; asm("mov.b64 %0, {%1, %2};" : "=l"(r) : "f"(lo), "f"(hi)); return r;
}
__device__ __forceinline__ void unpack2(u64 v, float& lo, float& hi) {
    asm("mov.b64 {%0, %1}, %2;" : "=f"(lo), "=f"(hi) : "l"(v));
}
__device__ __forceinline__ u64 ffma2(u64 a, u64 b, u64 c) {
    u64 d; asm("fma.rn.f32x2 %0, %1, %2, %3;" : "=l"(d) : "l"(a), "l"(b), "l"(c)); return d;
}

// ---------------- bf16 helpers ----------------
__device__ __forceinline__ uint32_t packbf(float o, float e) {   // low half = e
    uint32_t r; asm("cvt.rn.bf16x2.f32 %0, %1, %2;" : "=r"(r) : "f"(o), "f"(e)); return r;
}
// split packed f32 pair (even,odd) -> {hi bf16x2, lo bf16x2}
__device__ __forceinline__ void pair_split(u64 v, uint32_t& h, uint32_t& l) {
    float fe, fo; unpack2(v, fe, fo);
    h = packbf(fo, fe);
    float he = __uint_as_float(h << 16);
    float ho = __uint_as_float(h & 0xffff0000u);
    l = packbf(fo - ho, fe - he);
}
__device__ __forceinline__ uint32_t smem_u32(const void* p) {
    uint32_t a;
    asm("{ .reg .u64 t; cvta.to.shared.u64 t, %1; cvt.u32.u64 %0, t; }" : "=r"(a) : "l"(p));
    return a;
}
__device__ __forceinline__ void cp_async16(uint32_t dst, const void* src) {
    asm volatile("cp.async.ca.shared.global [%0], [%1], 16;" :: "r"(dst), "l"(src) : "memory");
}
__device__ __forceinline__ void cp_commit() {
    asm volatile("cp.async.commit_group;" ::: "memory");
}
__device__ __forceinline__ void cp_wait1() {
    asm volatile("cp.async.wait_group 1;" ::: "memory");
}
__device__ __forceinline__ void cp_wait0() {
    asm volatile("cp.async.wait_group 0;" ::: "memory");
}
// m16n8k16 bf16 mma, accumulate in place
__device__ __forceinline__ void mma16(float* c, const uint32_t* a, uint32_t b0, uint32_t b1) {
    asm volatile(
        "mma.sync.aligned.m16n8k16.row.col.f32.bf16.bf16.f32 "
        "{%0,%1,%2,%3}, {%4,%5,%6,%7}, {%8,%9}, {%0,%1,%2,%3};"
        : "+f"(c[0]), "+f"(c[1]), "+f"(c[2]), "+f"(c[3])
        : "r"(a[0]), "r"(a[1]), "r"(a[2]), "r"(a[3]), "r"(b0), "r"(b1));
}

// ---------------------------------------------------------------------------
// Kernel 1: stage 1 — gather + rank-32 outer product per node, bf16 hi/lo out.
// One warp per node; depth-8 gather pipeline. First 64 blocks also pack W.
// ---------------------------------------------------------------------------
__global__ __launch_bounds__(256) void stage1_kernel(
    const float* __restrict__ nodes,
    const int*   __restrict__ nlist,
    const float* __restrict__ edges,
    const float* __restrict__ w)
{
    // ---- embedded W pack (first 64 blocks; 16384 work items) ----
    if (blockIdx.x < 64) {
        int idx  = blockIdx.x * 256 + threadIdx.x;
        int lane = idx & 31;
        int nt   = (idx >> 5) & 7;
        int q    = (idx >> 8) & 1;
        int c    = idx >> 9;
        int tig  = lane & 3;
        int grp  = lane >> 2;
        int m    = nt * 8 + grp;
        int k0   = c * KCH + q * 16 + 2 * tig;
        float v[4];
#pragma unroll
        for (int s = 0; s < 4; ++s) {
            int k = k0 + (s >> 1) * 8 + (s & 1);
            int l = k >> 4, n = k & 15;
            v[s] = w[l * (FDIM * EDIM) + m * EDIM + n] * 0.03125f;
        }
        uint32_t b0h = packbf(v[1], v[0]);
        uint32_t b1h = packbf(v[3], v[2]);
        uint32_t b0l = packbf(v[1] - __uint_as_float(b0h & 0xffff0000u),
                              v[0] - __uint_as_float(b0h << 16));
        uint32_t b1l = packbf(v[3] - __uint_as_float(b1h & 0xffff0000u),
                              v[2] - __uint_as_float(b1h << 16));
        int base = ((c * 2 + q) * 2) * 8 + nt;
        g_Wp[(size_t)base * 32 + lane]       = make_uint2(b0h, b1h);
        g_Wp[(size_t)(base + 8) * 32 + lane] = make_uint2(b0l, b1l);
    }

    __shared__ float se[8][512];

    const int warp = threadIdx.x >> 5;
    const int lane = threadIdx.x & 31;
    const int node = (blockIdx.x << 3) + warp;
    const int b    = node >> 14;
    const float* nbase = nodes + (size_t)b * NPB * FDIM;

    const float4* e4 = (const float4*)(edges + (size_t)node * (KNB * EDIM));
    float4* s4 = (float4*)se[warp];
    s4[lane]       = e4[lane];
    s4[lane + 32]  = e4[lane + 32];
    s4[lane + 64]  = e4[lane + 64];
    s4[lane + 96]  = e4[lane + 96];
    int idx = nlist[node * KNB + lane];
    __syncwarp();

    u64 T0[8], T1[8];
#pragma unroll
    for (int p = 0; p < 8; ++p) { T0[p] = 0ull; T1[p] = 0ull; }

    float2 xq[8];
#pragma unroll
    for (int j = 0; j < 8; ++j) {
        int nb = __shfl_sync(0xffffffffu, idx, j);
        xq[j] = *(const float2*)(nbase + (size_t)nb * FDIM + 2 * lane);
    }

#pragma unroll
    for (int j = 0; j < KNB; ++j) {
        float2 xc = xq[j & 7];
        if (j + 8 < KNB) {
            int nb = __shfl_sync(0xffffffffu, idx, j + 8);
            xq[j & 7] = *(const float2*)(nbase + (size_t)nb * FDIM + 2 * lane);
        }
        u64 xx0 = pack2(xc.x, xc.x);
        u64 xx1 = pack2(xc.y, xc.y);
        const ulonglong2* ep = (const ulonglong2*)&se[warp][j * EDIM];
        ulonglong2 e01 = ep[0];
        ulonglong2 e23 = ep[1];
        ulonglong2 e45 = ep[2];
        ulonglong2 e67 = ep[3];
        T0[0] = ffma2(xx0, e01.x, T0[0]);  T0[1] = ffma2(xx0, e01.y, T0[1]);
        T0[2] = ffma2(xx0, e23.x, T0[2]);  T0[3] = ffma2(xx0, e23.y, T0[3]);
        T0[4] = ffma2(xx0, e45.x, T0[4]);  T0[5] = ffma2(xx0, e45.y, T0[5]);
        T0[6] = ffma2(xx0, e67.x, T0[6]);  T0[7] = ffma2(xx0, e67.y, T0[7]);
        T1[0] = ffma2(xx1, e01.x, T1[0]);  T1[1] = ffma2(xx1, e01.y, T1[1]);
        T1[2] = ffma2(xx1, e23.x, T1[2]);  T1[3] = ffma2(xx1, e23.y, T1[3]);
        T1[4] = ffma2(xx1, e45.x, T1[4]);  T1[5] = ffma2(xx1, e45.y, T1[5]);
        T1[6] = ffma2(xx1, e67.x, T1[6]);  T1[7] = ffma2(xx1, e67.y, T1[7]);
    }

    // split to bf16 hi/lo pairs and store lane's chunk (k = 32*lane..+31):
    // layout per node: [chunk(=lane)][pair j 0..15][{hi,lo}] u32, 128 B / lane
    {
        uint32_t hv[16], lv[16];
#pragma unroll
        for (int p = 0; p < 8; ++p) pair_split(T0[p], hv[p],     lv[p]);
#pragma unroll
        for (int p = 0; p < 8; ++p) pair_split(T1[p], hv[8 + p], lv[8 + p]);
        uint4* tp = (uint4*)(g_Tb + (size_t)node * KDIM + lane * 32);
#pragma unroll
        for (int p = 0; p < 8; ++p)
            tp[p] = make_uint4(hv[2*p], lv[2*p], hv[2*p+1], lv[2*p+1]);
    }
}

// ---------------------------------------------------------------------------
// Kernel 2: bf16 mma.sync GEMM, 3-split fp32 emulation (AhBh + AlBh + AhBl).
// CTA: 64 rows x 64 cols, 128 threads, 2x2 warp grid (warp = 32 rows x 32 cols,
// 2 m-tiles x 4 n-tiles). Grid 512 -> ~3.5 CTAs/SM, ~14 warps/SM.
// A arrives pre-split from stage1: one LDS.64 = {hi,lo} fragment pair.
// ---------------------------------------------------------------------------
#define A_STRIDE 40                        // u32 per row (conflict-free)
#define A_BUF    (64 * A_STRIDE)           // u32 per buffer (2560)
#define B_BUF    2048                      // u32 per buffer
#define GEMM_SMEM (2 * A_BUF * 4 + 2 * B_BUF * 4)   // 36864 B

__global__ __launch_bounds__(128, 4) void gemm_bf16_kernel(float* __restrict__ out)
{
    extern __shared__ char smraw[];
    uint32_t* As = (uint32_t*)smraw;                       // [2][64][40]
    uint32_t* Bs = (uint32_t*)(smraw + 2 * A_BUF * 4);     // [2][2048]

    const int tid  = threadIdx.x;
    const int lane = tid & 31;
    const int wid  = tid >> 5;
    const int wm   = wid & 1;           // warp m-position (0/1 -> rows +0/+32)
    const int wn   = wid >> 1;          // warp n-position (0/1 -> cols +0/+32)
    const int tig  = lane & 3;
    const int grp  = lane >> 2;
    const int rbase = blockIdx.x * 64;

    // staging coords
    const int s_row  = tid >> 1;        // 0..63
    const int s_half = tid & 1;         // 16-u32 half of the 32-u32 row chunk
    const uint32_t* aSrc = g_Tb + (size_t)(rbase + s_row) * KDIM + s_half * 16;
    const char*     bSrc = (const char*)g_Wp;

    float acc[2][4][4];
#pragma unroll
    for (int mt = 0; mt < 2; ++mt)
#pragma unroll
        for (int nt = 0; nt < 4; ++nt)
#pragma unroll
            for (int r = 0; r < 4; ++r) acc[mt][nt][r] = 0.0f;

#define STAGE(c, buf)                                                          \
    do {                                                                       \
        uint32_t ad = smem_u32(As + (buf) * A_BUF + s_row * A_STRIDE + s_half * 16); \
        const uint32_t* as_ = aSrc + (c) * 32;                                 \
        _Pragma("unroll")                                                      \
        for (int i = 0; i < 4; ++i) cp_async16(ad + i * 16, as_ + i * 4);      \
        uint32_t bd = smem_u32(Bs + (buf) * B_BUF) + tid * 64;                 \
        const char* bs_ = bSrc + (size_t)(c) * 8192 + tid * 64;                \
        _Pragma("unroll")                                                      \
        for (int i = 0; i < 4; ++i) cp_async16(bd + i * 16, bs_ + i * 16);     \
        cp_commit();                                                           \
    } while (0)

    STAGE(0, 0);

    for (int c = 0; c < NC; ++c) {
        const int buf = c & 1;
        if (c + 1 < NC) { STAGE(c + 1, buf ^ 1); cp_wait1(); }
        else            { cp_wait0(); }
        __syncthreads();

        const uint32_t* Ab = As + buf * A_BUF;
        const uint32_t* Bb = Bs + buf * B_BUF;

#pragma unroll
        for (int q = 0; q < 2; ++q) {
            uint32_t ah[2][4], al[2][4];
#pragma unroll
            for (int mt = 0; mt < 2; ++mt) {
                const uint32_t* pr =
                    Ab + (wm * 32 + mt * 16 + grp) * A_STRIDE + q * 16 + 2 * tig;
                uint2 v0 = *(const uint2*)(pr);                      // row grp,   k pair
                uint2 v1 = *(const uint2*)(pr + 8 * A_STRIDE);       // row grp+8
                uint2 v2 = *(const uint2*)(pr + 8);                  // k pair +4 (k+8)
                uint2 v3 = *(const uint2*)(pr + 8 * A_STRIDE + 8);
                ah[mt][0] = v0.x; al[mt][0] = v0.y;
                ah[mt][1] = v1.x; al[mt][1] = v1.y;
                ah[mt][2] = v2.x; al[mt][2] = v2.y;
                ah[mt][3] = v3.x; al[mt][3] = v3.y;
            }
#pragma unroll
            for (int nt = 0; nt < 4; ++nt) {
                const int ntg = wn * 4 + nt;
                uint2 bh = *(const uint2*)(Bb + ((q * 2 + 0) * 8 + ntg) * 64 + lane * 2);
                uint2 bl = *(const uint2*)(Bb + ((q * 2 + 1) * 8 + ntg) * 64 + lane * 2);
#pragma unroll
                for (int mt = 0; mt < 2; ++mt) {
                    mma16(acc[mt][nt], ah[mt], bh.x, bh.y);
                    mma16(acc[mt][nt], al[mt], bh.x, bh.y);
                    mma16(acc[mt][nt], ah[mt], bl.x, bl.y);
                }
            }
        }
        __syncthreads();
    }

#pragma unroll
    for (int mt = 0; mt < 2; ++mt) {
#pragma unroll
        for (int nt = 0; nt < 4; ++nt) {
            int row = rbase + wm * 32 + mt * 16 + grp;
            int col = wn * 32 + nt * 8 + 2 * tig;
            *(float2*)(out + (size_t)row * FDIM + col) =
                make_float2(acc[mt][nt][0], acc[mt][nt][1]);
            *(float2*)(out + (size_t)(row + 8) * FDIM + col) =
                make_float2(acc[mt][nt][2], acc[mt][nt][3]);
        }
    }
#undef STAGE
}

// ---------------------------------------------------------------------------
extern "C" void kernel_launch(void* const* d_in, const int* in_sizes, int n_in,
                              void* d_out, int out_size) {
    const float* nodes = (const float*)d_in[0];   // [2,16384,64] f32
    const int*   nlist = (const int*)  d_in[1];   // [2,16384,32] i32
    const float* edges = (const float*)d_in[2];   // [2,16384,32,16] f32
    const float* w     = (const float*)d_in[3];   // [64,64,16] f32
    float* out = (float*)d_out;                   // [2,16384,64] f32

    cudaFuncSetAttribute(gemm_bf16_kernel,
                         cudaFuncAttributeMaxDynamicSharedMemorySize, GEMM_SMEM);

    stage1_kernel<<<NODES / 8, 256>>>(nodes, nlist, edges, w);
    gemm_bf16_kernel<<<NODES / 64, 128, GEMM_SMEM>>>(out);
}

// round 7
// speedup vs baseline: 1.3370x; 1.1338x over previous
#include <cuda_runtime.h>
#include <cstdint>

// Problem constants (fixed shapes)
#define NODES 32768       // B*N
#define NPB   16384       // nodes per batch
#define FDIM  64          // node feature dim (F)
#define EDIM  16          // edge feature dim (E)
#define KNB   32          // neighbors per node (K)
#define KDIM  1024        // F*E, GEMM reduction dim
#define KCH   32          // GEMM k-chunk
#define NC    (KDIM / KCH)
#define NTILE (NODES / 64)   // 512 GEMM row-tiles

// Scratch (allocation-free rule: __device__ globals)
// A in MMA-fragment order, grouped by 64-row GEMM tile:
//   g_Af[ ((tile*32 + c)*2 + q)*256 + r*4 + tig ]  (uint4)
//   uint4 = { hi(k=2tig), lo(2tig), hi(2tig+8), lo(2tig+8) }  rel. to q-block
__device__ __align__(128) uint4 g_Af[(size_t)NODES * KDIM / 4];   // 128 MB
// B packed per (c,q,nt,lane): uint4 { b0_hi, b1_hi, b0_lo, b1_lo }
__device__ __align__(128) uint4 g_Bf[NC * 2 * 8 * 32];            // 256 KB

typedef unsigned long long u64;

// ---------------- f32x2 helpers (stage 1) ----------------
__device__ __forceinline__ u64 pack2(float lo, float hi) {
    u64 r; asm("mov.b64 %0, {%1, %2};" : "=l"(r) : "f"(lo), "f"(hi)); return r;
}
__device__ __forceinline__ void unpack2(u64 v, float& lo, float& hi) {
    asm("mov.b64 {%0, %1}, %2;" : "=f"(lo), "=f"(hi) : "l"(v));
}
__device__ __forceinline__ u64 ffma2(u64 a, u64 b, u64 c) {
    u64 d; asm("fma.rn.f32x2 %0, %1, %2, %3;" : "=l"(d) : "l"(a), "l"(b), "l"(c)); return d;
}

// ---------------- bf16 helpers ----------------
__device__ __forceinline__ uint32_t packbf(float o, float e) {   // low half = e
    uint32_t r; asm("cvt.rn.bf16x2.f32 %0, %1, %2;" : "=r"(r) : "f"(o), "f"(e)); return r;
}
// split packed f32 pair (even,odd) -> {hi bf16x2, lo bf16x2}
__device__ __forceinline__ void pair_split(u64 v, uint32_t& h, uint32_t& l) {
    float fe, fo; unpack2(v, fe, fo);
    h = packbf(fo, fe);
    float he = __uint_as_float(h << 16);
    float ho = __uint_as_float(h & 0xffff0000u);
    l = packbf(fo - ho, fe - he);
}
// m16n8k16 bf16 mma, accumulate in place
__device__ __forceinline__ void mma16(float* c, uint32_t a0, uint32_t a1,
                                      uint32_t a2, uint32_t a3,
                                      uint32_t b0, uint32_t b1) {
    asm volatile(
        "mma.sync.aligned.m16n8k16.row.col.f32.bf16.bf16.f32 "
        "{%0,%1,%2,%3}, {%4,%5,%6,%7}, {%8,%9}, {%0,%1,%2,%3};"
        : "+f"(c[0]), "+f"(c[1]), "+f"(c[2]), "+f"(c[3])
        : "r"(a0), "r"(a1), "r"(a2), "r"(a3), "r"(b0), "r"(b1));
}

// ---------------------------------------------------------------------------
// Kernel 1: stage 1 — gather + rank-32 outer product per node; writes T as
// bf16 hi/lo in GEMM fragment order. First 64 blocks also pack W.
// ---------------------------------------------------------------------------
__global__ __launch_bounds__(256) void stage1_kernel(
    const float* __restrict__ nodes,
    const int*   __restrict__ nlist,
    const float* __restrict__ edges,
    const float* __restrict__ w)
{
    // ---- embedded W pack (first 64 blocks; 16384 work items) ----
    if (blockIdx.x < 64) {
        int idx  = blockIdx.x * 256 + threadIdx.x;
        int lane = idx & 31;
        int nt   = (idx >> 5) & 7;
        int q    = (idx >> 8) & 1;
        int c    = idx >> 9;
        int tig  = lane & 3;
        int grp  = lane >> 2;
        int m    = nt * 8 + grp;
        int k0   = c * KCH + q * 16 + 2 * tig;
        float v[4];
#pragma unroll
        for (int s = 0; s < 4; ++s) {
            int k = k0 + (s >> 1) * 8 + (s & 1);
            int l = k >> 4, n = k & 15;
            v[s] = w[l * (FDIM * EDIM) + m * EDIM + n] * 0.03125f;
        }
        uint32_t b0h = packbf(v[1], v[0]);
        uint32_t b1h = packbf(v[3], v[2]);
        uint32_t b0l = packbf(v[1] - __uint_as_float(b0h & 0xffff0000u),
                              v[0] - __uint_as_float(b0h << 16));
        uint32_t b1l = packbf(v[3] - __uint_as_float(b1h & 0xffff0000u),
                              v[2] - __uint_as_float(b1h << 16));
        g_Bf[((c * 2 + q) * 8 + nt) * 32 + lane] = make_uint4(b0h, b1h, b0l, b1l);
    }

    __shared__ float se[8][512];

    const int warp = threadIdx.x >> 5;
    const int lane = threadIdx.x & 31;
    const int node = (blockIdx.x << 3) + warp;
    const int b    = node >> 14;
    const float* nbase = nodes + (size_t)b * NPB * FDIM;

    const float4* e4 = (const float4*)(edges + (size_t)node * (KNB * EDIM));
    float4* s4 = (float4*)se[warp];
    s4[lane]       = e4[lane];
    s4[lane + 32]  = e4[lane + 32];
    s4[lane + 64]  = e4[lane + 64];
    s4[lane + 96]  = e4[lane + 96];
    int idx = nlist[node * KNB + lane];
    __syncwarp();

    u64 T0[8], T1[8];
#pragma unroll
    for (int p = 0; p < 8; ++p) { T0[p] = 0ull; T1[p] = 0ull; }

    float2 xq[8];
#pragma unroll
    for (int j = 0; j < 8; ++j) {
        int nb = __shfl_sync(0xffffffffu, idx, j);
        xq[j] = *(const float2*)(nbase + (size_t)nb * FDIM + 2 * lane);
    }

#pragma unroll
    for (int j = 0; j < KNB; ++j) {
        float2 xc = xq[j & 7];
        if (j + 8 < KNB) {
            int nb = __shfl_sync(0xffffffffu, idx, j + 8);
            xq[j & 7] = *(const float2*)(nbase + (size_t)nb * FDIM + 2 * lane);
        }
        u64 xx0 = pack2(xc.x, xc.x);
        u64 xx1 = pack2(xc.y, xc.y);
        const ulonglong2* ep = (const ulonglong2*)&se[warp][j * EDIM];
        ulonglong2 e01 = ep[0];
        ulonglong2 e23 = ep[1];
        ulonglong2 e45 = ep[2];
        ulonglong2 e67 = ep[3];
        T0[0] = ffma2(xx0, e01.x, T0[0]);  T0[1] = ffma2(xx0, e01.y, T0[1]);
        T0[2] = ffma2(xx0, e23.x, T0[2]);  T0[3] = ffma2(xx0, e23.y, T0[3]);
        T0[4] = ffma2(xx0, e45.x, T0[4]);  T0[5] = ffma2(xx0, e45.y, T0[5]);
        T0[6] = ffma2(xx0, e67.x, T0[6]);  T0[7] = ffma2(xx0, e67.y, T0[7]);
        T1[0] = ffma2(xx1, e01.x, T1[0]);  T1[1] = ffma2(xx1, e01.y, T1[1]);
        T1[2] = ffma2(xx1, e23.x, T1[2]);  T1[3] = ffma2(xx1, e23.y, T1[3]);
        T1[4] = ffma2(xx1, e45.x, T1[4]);  T1[5] = ffma2(xx1, e45.y, T1[5]);
        T1[6] = ffma2(xx1, e67.x, T1[6]);  T1[7] = ffma2(xx1, e67.y, T1[7]);
    }

    // bf16 hi/lo split; write GEMM-fragment-order uint4s.
    // T0[p] = q=0, rel k-pair p; T1[p] = q=1, rel k-pair p (lane = chunk c).
    {
        uint32_t hv[16], lv[16];
#pragma unroll
        for (int p = 0; p < 8; ++p) pair_split(T0[p], hv[p],     lv[p]);
#pragma unroll
        for (int p = 0; p < 8; ++p) pair_split(T1[p], hv[8 + p], lv[8 + p]);

        const int tile = node >> 6;
        const int r    = node & 63;
        uint4* base = g_Af + ((size_t)(tile * 32 + lane) * 2) * 256 + r * 4;
#pragma unroll
        for (int q = 0; q < 2; ++q)
#pragma unroll
            for (int t = 0; t < 4; ++t)
                base[q * 256 + t] = make_uint4(hv[q * 8 + t],     lv[q * 8 + t],
                                               hv[q * 8 + t + 4], lv[q * 8 + t + 4]);
    }
}

// ---------------------------------------------------------------------------
// Kernel 2: bf16 mma.sync GEMM, 3-split fp32 emulation (AhBh + AlBh + AhBl).
// No shared memory: A and B read directly from gmem in fragment order.
// CTA: 64 rows x 64 cols, 4 warps (2x2), warp = 32x32 (2 mt x 4 nt).
// Per warp-chunk: 16 LDG.128 + 48 HMMA. Warps fully independent.
// ---------------------------------------------------------------------------
__global__ __launch_bounds__(128, 4) void gemm_bf16_kernel(float* __restrict__ out)
{
    const int tid  = threadIdx.x;
    const int lane = tid & 31;
    const int wid  = tid >> 5;
    const int wm   = wid & 1;
    const int wn   = wid >> 1;
    const int tig  = lane & 3;
    const int grp  = lane >> 2;
    const int tile = blockIdx.x;

    const uint4* Abase = g_Af + (size_t)tile * 32 * 2 * 256;
    // lane-linear fragment address: row*4 + tig  ==  base + lane when rows = grp
    const int aoff0 = (wm * 32 + grp) * 4 + tig;        // mt=0, rows grp
    const int aoff8 = aoff0 + 32;                       // rows grp+8

    float acc[2][4][4];
#pragma unroll
    for (int mt = 0; mt < 2; ++mt)
#pragma unroll
        for (int nt = 0; nt < 4; ++nt)
#pragma unroll
            for (int r = 0; r < 4; ++r) acc[mt][nt][r] = 0.0f;

#pragma unroll 2
    for (int c = 0; c < NC; ++c) {
#pragma unroll
        for (int q = 0; q < 2; ++q) {
            const uint4* blk = Abase + (c * 2 + q) * 256;
            uint4 a[2][2];
#pragma unroll
            for (int mt = 0; mt < 2; ++mt) {
                a[mt][0] = blk[aoff0 + mt * 64];        // rows grp   (+16 per mt)
                a[mt][1] = blk[aoff8 + mt * 64];        // rows grp+8
            }
            uint4 bv[4];
#pragma unroll
            for (int nt = 0; nt < 4; ++nt)
                bv[nt] = g_Bf[((c * 2 + q) * 8 + wn * 4 + nt) * 32 + lane];
#pragma unroll
            for (int nt = 0; nt < 4; ++nt) {
#pragma unroll
                for (int mt = 0; mt < 2; ++mt) {
                    // hi A frag: {a0,a1,a2,a3} ; lo A frag from .y/.w
                    mma16(acc[mt][nt], a[mt][0].x, a[mt][1].x, a[mt][0].z, a[mt][1].z,
                          bv[nt].x, bv[nt].y);
                    mma16(acc[mt][nt], a[mt][0].y, a[mt][1].y, a[mt][0].w, a[mt][1].w,
                          bv[nt].x, bv[nt].y);
                    mma16(acc[mt][nt], a[mt][0].x, a[mt][1].x, a[mt][0].z, a[mt][1].z,
                          bv[nt].z, bv[nt].w);
                }
            }
        }
    }

    // epilogue
    const int rbase = tile * 64;
#pragma unroll
    for (int mt = 0; mt < 2; ++mt) {
#pragma unroll
        for (int nt = 0; nt < 4; ++nt) {
            int row = rbase + wm * 32 + mt * 16 + grp;
            int col = wn * 32 + nt * 8 + 2 * tig;
            *(float2*)(out + (size_t)row * FDIM + col) =
                make_float2(acc[mt][nt][0], acc[mt][nt][1]);
            *(float2*)(out + (size_t)(row + 8) * FDIM + col) =
                make_float2(acc[mt][nt][2], acc[mt][nt][3]);
        }
    }
}

// ---------------------------------------------------------------------------
extern "C" void kernel_launch(void* const* d_in, const int* in_sizes, int n_in,
                              void* d_out, int out_size) {
    const float* nodes = (const float*)d_in[0];   // [2,16384,64] f32
    const int*   nlist = (const int*)  d_in[1];   // [2,16384,32] i32
    const float* edges = (const float*)d_in[2];   // [2,16384,32,16] f32
    const float* w     = (const float*)d_in[3];   // [64,64,16] f32
    float* out = (float*)d_out;                   // [2,16384,64] f32

    stage1_kernel<<<NODES / 8, 256>>>(nodes, nlist, edges, w);
    gemm_bf16_kernel<<<NTILE, 128>>>(out);
}